// round 10
// baseline (speedup 1.0000x reference)
#include <cuda_runtime.h>
#include <cuda_bf16.h>
#include <math.h>

#define IN_CH 128
#define H 4
#define C 16
#define HC 64
#define MAXN 100000
#define MAXE 1600000
#define NEG_SLOPE 0.2f
#define SCAN_BLK 512
#define FDEG 32          // cached slots per node in fuse

// scratch (device globals — allocation is forbidden)
__device__ __align__(16) float g_xp[MAXN * HC];      // 25.6 MB
__device__ __align__(16) float g_asrc[MAXN * H];
__device__ __align__(16) float g_adst[MAXN * H];
__device__ int  g_cnt[MAXN];        // zero-initialized; self-restored each call
__device__ int  g_rowptr[MAXN];     // partial (within-block) exclusive prefix
__device__ int  g_woff[MAXN];       // copy of partial prefix, atomically bumped
__device__ int  g_bsum[SCAN_BLK];
__device__ int  g_boff[SCAN_BLK];
__device__ int  g_scancnt;          // block-done counter; self-restored
__device__ int2 g_sedge[MAXE];      // (src, orig edge id), dst-sorted

__device__ __forceinline__ float4 leaky_exp4(float4 as, float4 ad) {
    float4 l;
    l.x = as.x + ad.x; l.x = l.x > 0.f ? l.x : NEG_SLOPE * l.x;
    l.y = as.y + ad.y; l.y = l.y > 0.f ? l.y : NEG_SLOPE * l.y;
    l.z = as.z + ad.z; l.z = l.z > 0.f ? l.z : NEG_SLOPE * l.z;
    l.w = as.w + ad.w; l.w = l.w > 0.f ? l.w : NEG_SLOPE * l.w;
    float4 ev;
    ev.x = __expf(l.x); ev.y = __expf(l.y);
    ev.z = __expf(l.z); ev.w = __expf(l.w);
    return ev;
}

// ---------------------------------------------------------------------------
// K-hist: histogram of dst (int4, 4 atomics/thread). dst half only.
// ---------------------------------------------------------------------------
__global__ void k_hist4(const int* __restrict__ ei, int e) {
    const int4* d4p = (const int4*)(ei + e);   // e % 4 == 0 checked on host
    int q = e >> 2;
    for (int i = blockIdx.x * blockDim.x + threadIdx.x; i < q;
         i += gridDim.x * blockDim.x) {
        int4 d = d4p[i];
        atomicAdd(&g_cnt[d.x], 1);
        atomicAdd(&g_cnt[d.y], 1);
        atomicAdd(&g_cnt[d.z], 1);
        atomicAdd(&g_cnt[d.w], 1);
    }
}
__global__ void k_hist1(const int* __restrict__ ei, int e) {   // fallback
    for (int i = blockIdx.x * blockDim.x + threadIdx.x; i < e;
         i += gridDim.x * blockDim.x)
        atomicAdd(&g_cnt[ei[e + i]], 1);
}

// ---------------------------------------------------------------------------
// K-scan: per-block exclusive scan of g_cnt (self-zeroing) -> rowptr/woff
// (partial); last finished block scans the block sums -> g_boff.
// Final rowptr value = partial + g_boff[i >> 9] (consumers add inline).
// ---------------------------------------------------------------------------
__global__ __launch_bounds__(SCAN_BLK) void k_scan(int n) {
    __shared__ int s[SCAN_BLK];
    __shared__ int lastdone;
    int t = threadIdx.x;
    int i = blockIdx.x * SCAN_BLK + t;
    int v = 0;
    if (i < n) {
        v = g_cnt[i];
        g_cnt[i] = 0;               // restore invariant for next call
    }
    s[t] = v;
    __syncthreads();
    #pragma unroll
    for (int off = 1; off < SCAN_BLK; off <<= 1) {
        int a = (t >= off) ? s[t - off] : 0;
        __syncthreads();
        s[t] += a;
        __syncthreads();
    }
    if (i < n) {
        int r = s[t] - v;           // exclusive within block
        g_rowptr[i] = r;
        g_woff[i] = r;
    }
    if (t == SCAN_BLK - 1) g_bsum[blockIdx.x] = s[t];

    __threadfence();
    if (t == 0) {
        int d = atomicAdd(&g_scancnt, 1);
        lastdone = (d == gridDim.x - 1);
    }
    __syncthreads();
    if (!lastdone) return;
    int nb = gridDim.x;
    int bv = (t < nb) ? g_bsum[t] : 0;
    s[t] = bv;
    __syncthreads();
    #pragma unroll
    for (int off = 1; off < SCAN_BLK; off <<= 1) {
        int a = (t >= off) ? s[t - off] : 0;
        __syncthreads();
        s[t] += a;
        __syncthreads();
    }
    g_boff[t] = s[t] - bv;
    if (t == 0) g_scancnt = 0;
}

// ---------------------------------------------------------------------------
// K-permute: 4 edges/thread (int4 loads), scatter into dst-sorted order,
// and produce the edge_index float copy (coalesced float4 stores).
// ---------------------------------------------------------------------------
__global__ void k_permute4(const int* __restrict__ ei,
                           float* __restrict__ out_ei, int e) {
    int q = e >> 2;
    int i = blockIdx.x * blockDim.x + threadIdx.x;
    if (i >= q) return;
    int4 s4 = ((const int4*)ei)[i];
    int4 d4 = ((const int4*)(ei + e))[i];
    if (out_ei) {
        float4 fs = make_float4((float)s4.x, (float)s4.y,
                                (float)s4.z, (float)s4.w);
        float4 fd = make_float4((float)d4.x, (float)d4.y,
                                (float)d4.z, (float)d4.w);
        ((float4*)out_ei)[i] = fs;
        ((float4*)(out_ei + e))[i] = fd;
    }
    int base = i * 4;
    int r0 = atomicAdd(&g_woff[d4.x], 1) + g_boff[d4.x >> 9];
    int r1 = atomicAdd(&g_woff[d4.y], 1) + g_boff[d4.y >> 9];
    int r2 = atomicAdd(&g_woff[d4.z], 1) + g_boff[d4.z >> 9];
    int r3 = atomicAdd(&g_woff[d4.w], 1) + g_boff[d4.w >> 9];
    g_sedge[r0] = make_int2(s4.x, base);
    g_sedge[r1] = make_int2(s4.y, base + 1);
    g_sedge[r2] = make_int2(s4.z, base + 2);
    g_sedge[r3] = make_int2(s4.w, base + 3);
}
__global__ void k_permute1(const int* __restrict__ ei,
                           float* __restrict__ out_ei, int e) {  // fallback
    int i = blockIdx.x * blockDim.x + threadIdx.x;
    if (i >= e) return;
    int src = ei[i], dst = ei[e + i];
    if (out_ei) { out_ei[i] = (float)src; out_ei[e + i] = (float)dst; }
    int r = atomicAdd(&g_woff[dst], 1) + g_boff[dst >> 9];
    g_sedge[r] = make_int2(src, i);
}

// ---------------------------------------------------------------------------
// K-gemm: xp = x @ W, fused a_src/a_dst. 128 nodes/block, 4x8 tile/thread
// ---------------------------------------------------------------------------
__global__ __launch_bounds__(256) void k_gemm(
        const float* __restrict__ x, const float* __restrict__ W,
        const float* __restrict__ att_src, const float* __restrict__ att_dst,
        int n) {
    __shared__ float4 sW4[IN_CH * 16];      // 32 KB
    __shared__ float  sx[128 * 129];        // 66 KB
    int tid = threadIdx.x;
    int tx = tid & 7;
    int ty = tid >> 3;
    int node0 = blockIdx.x * 128;

    const float4* W4 = (const float4*)W;
    #pragma unroll
    for (int i = 0; i < (IN_CH * 16) / 256; i++)
        sW4[tid + i * 256] = W4[tid + i * 256];

    #pragma unroll
    for (int i = 0; i < (128 * IN_CH) / 256; i++) {
        int idx = tid + i * 256;
        int nn = idx >> 7, k = idx & 127;
        int node = node0 + nn;
        sx[nn * 129 + k] = (node < n) ? x[(size_t)node * IN_CH + k] : 0.f;
    }
    __syncthreads();

    float4 acc[4][2];
    #pragma unroll
    for (int j = 0; j < 4; j++) {
        acc[j][0] = make_float4(0.f, 0.f, 0.f, 0.f);
        acc[j][1] = make_float4(0.f, 0.f, 0.f, 0.f);
    }

    #pragma unroll 4
    for (int k = 0; k < IN_CH; k++) {
        float4 w0 = sW4[k * 16 + 2 * tx];
        float4 w1 = sW4[k * 16 + 2 * tx + 1];
        #pragma unroll
        for (int j = 0; j < 4; j++) {
            float xv = sx[(ty * 4 + j) * 129 + k];
            acc[j][0].x = fmaf(xv, w0.x, acc[j][0].x);
            acc[j][0].y = fmaf(xv, w0.y, acc[j][0].y);
            acc[j][0].z = fmaf(xv, w0.z, acc[j][0].z);
            acc[j][0].w = fmaf(xv, w0.w, acc[j][0].w);
            acc[j][1].x = fmaf(xv, w1.x, acc[j][1].x);
            acc[j][1].y = fmaf(xv, w1.y, acc[j][1].y);
            acc[j][1].z = fmaf(xv, w1.z, acc[j][1].z);
            acc[j][1].w = fmaf(xv, w1.w, acc[j][1].w);
        }
    }

    float4 as0 = ((const float4*)att_src)[2 * tx];
    float4 as1 = ((const float4*)att_src)[2 * tx + 1];
    float4 ad0 = ((const float4*)att_dst)[2 * tx];
    float4 ad1 = ((const float4*)att_dst)[2 * tx + 1];
    int head = tx >> 1;

    #pragma unroll
    for (int j = 0; j < 4; j++) {
        int node = node0 + ty * 4 + j;
        if (node < n) {
            ((float4*)g_xp)[(size_t)node * 16 + 2 * tx]     = acc[j][0];
            ((float4*)g_xp)[(size_t)node * 16 + 2 * tx + 1] = acc[j][1];
        }
        float s = acc[j][0].x * as0.x + acc[j][0].y * as0.y +
                  acc[j][0].z * as0.z + acc[j][0].w * as0.w +
                  acc[j][1].x * as1.x + acc[j][1].y * as1.y +
                  acc[j][1].z * as1.z + acc[j][1].w * as1.w;
        float d = acc[j][0].x * ad0.x + acc[j][0].y * ad0.y +
                  acc[j][0].z * ad0.z + acc[j][0].w * ad0.w +
                  acc[j][1].x * ad1.x + acc[j][1].y * ad1.y +
                  acc[j][1].z * ad1.z + acc[j][1].w * ad1.w;
        s += __shfl_xor_sync(0xffffffffu, s, 1);
        d += __shfl_xor_sync(0xffffffffu, d, 1);
        if ((tx & 1) == 0 && node < n) {
            g_asrc[node * H + head] = s;
            g_adst[node * H + head] = d;
        }
    }
}

// ---------------------------------------------------------------------------
// K-fuse: HALF-WARP (16 lanes) per dst node. Lane owns float4 (4 cols).
// Pass 1: ev cached in smem (32 slots/node), 16-lane reduce for denom.
// Pass 2: one edge per group-iteration; owner lane writes alpha float4;
//         src broadcast via LDS; acc += xp[src]*alpha; out = acc + bias.
// ---------------------------------------------------------------------------
__global__ __launch_bounds__(256) void k_fuse(
        const float* __restrict__ bias, float* __restrict__ out,
        float* __restrict__ out_alpha, int n, int e) {
    __shared__ float4 s_ev[16][FDEG];   // 8 KB
    __shared__ int2   s_se[16][FDEG];   // 4 KB
    int g = threadIdx.x >> 4;           // group 0..15
    int l = threadIdx.x & 15;           // lane within group
    unsigned gmask = 0xFFFFu << ((g & 1) * 16);
    int node = blockIdx.x * 16 + g;
    if (node >= n) return;
    int start = g_rowptr[node] + g_boff[node >> 9];
    int end = (node == n - 1) ? e
            : g_rowptr[node + 1] + g_boff[(node + 1) >> 9];
    int deg = end - start;
    float4 ad = ((const float4*)g_adst)[node];

    // pass 1: ev cache + denominator
    float4 sum = make_float4(0.f, 0.f, 0.f, 0.f);
    for (int slot = l; slot < deg; slot += 16) {
        int2 se = g_sedge[start + slot];
        float4 as = ((const float4*)g_asrc)[se.x];
        float4 ev = leaky_exp4(as, ad);
        if (slot < FDEG) {
            s_ev[g][slot] = ev;
            s_se[g][slot] = se;
        }
        sum.x += ev.x; sum.y += ev.y; sum.z += ev.z; sum.w += ev.w;
    }
    #pragma unroll
    for (int off = 8; off >= 1; off >>= 1) {
        sum.x += __shfl_xor_sync(gmask, sum.x, off);
        sum.y += __shfl_xor_sync(gmask, sum.y, off);
        sum.z += __shfl_xor_sync(gmask, sum.z, off);
        sum.w += __shfl_xor_sync(gmask, sum.w, off);
    }
    float4 inv;
    inv.x = 1.f / (sum.x + 1e-16f);
    inv.y = 1.f / (sum.y + 1e-16f);
    inv.z = 1.f / (sum.z + 1e-16f);
    inv.w = 1.f / (sum.w + 1e-16f);
    __syncwarp(gmask);

    int h = l >> 2;                      // head for my float4
    float invh = (h == 0) ? inv.x : (h == 1) ? inv.y :
                 (h == 2) ? inv.z : inv.w;
    float4 acc = make_float4(0.f, 0.f, 0.f, 0.f);

    for (int base = 0; base < deg; base += 16) {
        int m = deg - base; if (m > 16) m = 16;
        int slot = base + l;
        // overflow slots (deg > FDEG): recompute into wrapped region
        if (slot >= FDEG && l < m) {
            int2 se = g_sedge[start + slot];
            float4 as = ((const float4*)g_asrc)[se.x];
            s_ev[g][slot & (FDEG - 1)] = leaky_exp4(as, ad);
            s_se[g][slot & (FDEG - 1)] = se;
        }
        __syncwarp(gmask);
        if (l < m && out_alpha) {
            int idx = slot & (FDEG - 1);
            float4 ev = s_ev[g][idx];
            float4 al;
            al.x = ev.x * inv.x; al.y = ev.y * inv.y;
            al.z = ev.z * inv.z; al.w = ev.w * inv.w;
            ((float4*)out_alpha)[s_se[g][idx].y] = al;
        }
        #pragma unroll 4
        for (int j = 0; j < m; j++) {
            int idx = (base + j) & (FDEG - 1);
            int src = s_se[g][idx].x;                      // LDS broadcast
            float a = ((const float*)&s_ev[g][idx])[h] * invh;
            float4 v = ((const float4*)&g_xp[(size_t)src * HC])[l];
            acc.x = fmaf(v.x, a, acc.x);
            acc.y = fmaf(v.y, a, acc.y);
            acc.z = fmaf(v.z, a, acc.z);
            acc.w = fmaf(v.w, a, acc.w);
        }
        __syncwarp(gmask);
    }
    float4 b = ((const float4*)bias)[l];
    float4 o;
    o.x = acc.x + b.x; o.y = acc.y + b.y;
    o.z = acc.z + b.z; o.w = acc.w + b.w;
    ((float4*)&out[(size_t)node * HC])[l] = o;
}

// lazily-created side stream + events (resource init only; the launched work
// is identical on every call, so graph capture sees the same graph each time)
static cudaStream_t g_s2 = nullptr;
static cudaEvent_t  g_evFork = nullptr, g_evJoin = nullptr;

extern "C" void kernel_launch(void* const* d_in, const int* in_sizes, int n_in,
                              void* d_out, int out_size) {
    const float* x       = (const float*)d_in[0];
    const float* W       = (const float*)d_in[1];
    const float* att_src = (const float*)d_in[2];
    const float* att_dst = (const float*)d_in[3];
    const float* bias    = (const float*)d_in[4];
    const int*   ei      = (const int*)d_in[5];

    if (!g_s2) {
        cudaStreamCreateWithFlags(&g_s2, cudaStreamNonBlocking);
        cudaEventCreateWithFlags(&g_evFork, cudaEventDisableTiming);
        cudaEventCreateWithFlags(&g_evJoin, cudaEventDisableTiming);
    }

    int n = in_sizes[0] / IN_CH;
    int e = in_sizes[5] / 2;

    float* out = (float*)d_out;
    float* out_ei = nullptr;
    float* out_alpha = nullptr;
    if (out_size >= n * HC + 2 * e) out_ei = out + (size_t)n * HC;
    if (out_size >= n * HC + 2 * e + e * H)
        out_alpha = out + (size_t)n * HC + 2 * e;

    // ---- fork: GEMM on side stream (independent of CSR build) ----
    cudaEventRecord(g_evFork, 0);
    cudaStreamWaitEvent(g_s2, g_evFork, 0);
    k_gemm<<<(n + 127) / 128, 256, 0, g_s2>>>(x, W, att_src, att_dst, n);
    cudaEventRecord(g_evJoin, g_s2);

    // ---- main stream: CSR build ----
    bool vec = ((e & 3) == 0);
    if (vec) {
        int q = e >> 2;
        int blocks = (q + 255) / 256;
        if (blocks > 2048) blocks = 2048;
        k_hist4<<<blocks, 256>>>(ei, e);
    } else {
        int blocks = (e + 255) / 256;
        if (blocks > 4096) blocks = 4096;
        k_hist1<<<blocks, 256>>>(ei, e);
    }
    int nb = (n + SCAN_BLK - 1) / SCAN_BLK;
    k_scan<<<nb, SCAN_BLK>>>(n);
    if (vec) {
        int q = e >> 2;
        k_permute4<<<(q + 255) / 256, 256>>>(ei, out_ei, e);
    } else {
        k_permute1<<<(e + 255) / 256, 256>>>(ei, out_ei, e);
    }

    // ---- join: fuse needs both GEMM results and sorted edges ----
    cudaStreamWaitEvent(0, g_evJoin, 0);
    k_fuse<<<(n + 15) / 16, 256>>>(bias, out, out_alpha, n, e);
}